// round 1
// baseline (speedup 1.0000x reference)
#include <cuda_runtime.h>
#include <cuda_bf16.h>

#define M_SEG 16

// Precomputed per-segment affine coefficients: out = c0[j] + c1[j] * S
__device__ float g_c0[M_SEG];
__device__ float g_c1[M_SEG];

__global__ void setup_coeffs_kernel(const float* __restrict__ u)
{
    if (threadIdx.x != 0 || blockIdx.x != 0) return;

    const float delta = 1.0f / (float)M_SEG;
    float a[M_SEG];
    float sum = 0.0f;
#pragma unroll
    for (int i = 0; i < M_SEG; ++i) {
        float s = 1.0f / (1.0f + expf(-u[i]));   // sigmoid
        a[i] = 0.5f + 4.5f * s;                  // A_MIN + (A_MAX-A_MIN)*sig
        sum += a[i];
    }
    const float Y = sum * delta;
    const float invY = 1.0f / Y;

    float cum = 0.0f;                             // cum[j] = sum_{i<j} a_i*delta
#pragma unroll
    for (int j = 0; j < M_SEG; ++j) {
        float bj = (float)j * delta;
        g_c0[j] = (cum - a[j] * bj) * invY;
        g_c1[j] = a[j] * invY;
        cum += a[j] * delta;
    }
}

__device__ __forceinline__ float map_one(float s, const float* s0, const float* s1)
{
    int j = (int)(s * (float)M_SEG);              // exact: bounds are k/16, *16 is pow2
    j = min(max(j, 0), M_SEG - 1);
    return fmaf(s1[j], s, s0[j]);
}

__global__ void __launch_bounds__(256) map_kernel(const float4* __restrict__ S,
                                                  float4* __restrict__ out,
                                                  int n4)
{
    __shared__ float s0[M_SEG];
    __shared__ float s1[M_SEG];
    if (threadIdx.x < M_SEG) {
        s0[threadIdx.x] = g_c0[threadIdx.x];
        s1[threadIdx.x] = g_c1[threadIdx.x];
    }
    __syncthreads();

    int i = blockIdx.x * blockDim.x + threadIdx.x;
    if (i < n4) {
        float4 v = S[i];
        float4 r;
        r.x = map_one(v.x, s0, s1);
        r.y = map_one(v.y, s0, s1);
        r.z = map_one(v.z, s0, s1);
        r.w = map_one(v.w, s0, s1);
        out[i] = r;
    }
}

__global__ void map_tail_kernel(const float* __restrict__ S,
                                float* __restrict__ out,
                                int start, int n)
{
    __shared__ float s0[M_SEG];
    __shared__ float s1[M_SEG];
    if (threadIdx.x < M_SEG) {
        s0[threadIdx.x] = g_c0[threadIdx.x];
        s1[threadIdx.x] = g_c1[threadIdx.x];
    }
    __syncthreads();
    int i = start + blockIdx.x * blockDim.x + threadIdx.x;
    if (i < n) out[i] = map_one(S[i], s0, s1);
}

extern "C" void kernel_launch(void* const* d_in, const int* in_sizes, int n_in,
                              void* d_out, int out_size)
{
    const float* S = (const float*)d_in[0];
    const float* u = (const float*)d_in[1];
    float* out = (float*)d_out;

    int n = in_sizes[0];

    setup_coeffs_kernel<<<1, 32>>>(u);

    int n4 = n / 4;
    if (n4 > 0) {
        int threads = 256;
        int blocks = (n4 + threads - 1) / threads;
        map_kernel<<<blocks, threads>>>((const float4*)S, (float4*)out, n4);
    }
    int tail = n - n4 * 4;
    if (tail > 0) {
        map_tail_kernel<<<1, 256>>>(S, out, n4 * 4, n);
    }
}

// round 4
// speedup vs baseline: 1.1456x; 1.1456x over previous
#include <cuda_runtime.h>
#include <cuda_bf16.h>

#define M_SEG 16

// Warp-0 computes the 16 affine coefficients (c0,c1) into shared:
//   out = c0[j] + c1[j]*S,   j = floor(S*16) clamped to [0,15]
//   c1[j] = a[j]/Y,  c0[j] = (cum_excl[j] - a[j]*j/16)/Y
__device__ __forceinline__ void build_coeffs(float2* sc, const float* __restrict__ u)
{
    int t = threadIdx.x;
    if (t < 32) {
        int lane = t;
        float uu = __ldg(&u[lane & (M_SEG - 1)]);
        float sig = 1.0f / (1.0f + __expf(-uu));
        float a = 0.5f + 4.5f * sig;                 // A_MIN + (A_MAX-A_MIN)*sigmoid
        float seg = (lane < M_SEG) ? a * (1.0f / M_SEG) : 0.0f;

        // inclusive scan of seg over lanes 0..15
        float v = seg;
        #pragma unroll
        for (int off = 1; off < M_SEG; off <<= 1) {
            float nb = __shfl_up_sync(0xffffffffu, v, off);
            if (lane >= off) v += nb;
        }
        float Y = __shfl_sync(0xffffffffu, v, M_SEG - 1);
        float invY = 1.0f / Y;
        if (lane < M_SEG) {
            float excl = v - seg;                    // cum before segment `lane`
            float c1 = a * invY;
            float c0 = (excl - a * (float)lane * (1.0f / M_SEG)) * invY;
            sc[lane] = make_float2(c0, c1);
        }
    }
    __syncthreads();
}

__device__ __forceinline__ float map_one(float s, const float2* sc)
{
    int j = (int)(s * (float)M_SEG);                 // exact: bounds are k/16
    j = min(max(j, 0), M_SEG - 1);
    float2 c = sc[j];
    return fmaf(c.y, s, c.x);
}

__device__ __forceinline__ float4 map_vec(float4 v, const float2* sc)
{
    float4 r;
    r.x = map_one(v.x, sc);
    r.y = map_one(v.y, sc);
    r.z = map_one(v.z, sc);
    r.w = map_one(v.w, sc);
    return r;
}

// Each thread handles 2 float4 (independent, front-batched loads -> MLP=2)
__global__ void __launch_bounds__(256) map_kernel(const float4* __restrict__ S,
                                                  float4* __restrict__ out,
                                                  int n4,
                                                  const float* __restrict__ u)
{
    __shared__ float2 sc[M_SEG];
    build_coeffs(sc, u);

    int stride = gridDim.x * blockDim.x;
    int i0 = blockIdx.x * blockDim.x + threadIdx.x;
    int i1 = i0 + stride;

    bool p0 = i0 < n4;
    bool p1 = i1 < n4;
    float4 v0, v1;
    if (p0) v0 = S[i0];
    if (p1) v1 = S[i1];

    if (p0) out[i0] = map_vec(v0, sc);
    if (p1) out[i1] = map_vec(v1, sc);
}

// Scalar tail (only launched when n % 4 != 0)
__global__ void __launch_bounds__(256) map_tail_kernel(const float* __restrict__ S,
                                                       float* __restrict__ out,
                                                       int start, int n,
                                                       const float* __restrict__ u)
{
    __shared__ float2 sc[M_SEG];
    build_coeffs(sc, u);
    int i = start + blockIdx.x * blockDim.x + threadIdx.x;
    if (i < n) out[i] = map_one(S[i], sc);
}

extern "C" void kernel_launch(void* const* d_in, const int* in_sizes, int n_in,
                              void* d_out, int out_size)
{
    const float* S = (const float*)d_in[0];
    const float* u = (const float*)d_in[1];
    float* out = (float*)d_out;

    int n = in_sizes[0];
    int n4 = n / 4;

    if (n4 > 0) {
        const int threads = 256;
        const int per_block = threads * 2;           // 2 float4 per thread
        int blocks = (n4 + per_block - 1) / per_block;
        map_kernel<<<blocks, threads>>>((const float4*)S, (float4*)out, n4, u);
    }
    int tail = n - n4 * 4;
    if (tail > 0) {
        map_tail_kernel<<<1, 256>>>(S, out, n4 * 4, n, u);
    }
}